// round 13
// baseline (speedup 1.0000x reference)
#include <cuda_runtime.h>
#include <cuda_fp16.h>
#include <math.h>
#include <stdint.h>

#define S_LEN   4096
#define D_IN    2048
#define D_Q     2048
#define D_KV    512
#define N_HEADS 32
#define N_KV    8
#define HDIM    64

// Scratch (device globals: allocation-free per harness rules)
__device__ __half g_xh  [S_LEN * D_IN];          // x, fp16
__device__ __half g_wqkT[(D_Q + D_KV) * D_IN];   // [Wq^T ; Wk^T] fp16 [N][K]
__device__ __half g_wvT [D_KV * D_IN];
__device__ __half g_woT [D_Q  * D_Q];
__device__ __half g_qh  [S_LEN * D_Q];           // q fp16, pre-scaled 1/8
__device__ __half g_kh  [S_LEN * D_KV];          // k fp16
__device__ __half g_vt  [D_KV * S_LEN];          // v fp16 transposed [d][s]
__device__ __half g_ctx [S_LEN * D_Q];           // attention out fp16

// ---------------------------------------------------------------------------
// helpers
// ---------------------------------------------------------------------------
__device__ __forceinline__ uint32_t h2ex2(uint32_t x) {
    uint32_t y;
    asm("ex2.approx.f16x2 %0, %1;" : "=r"(y) : "r"(x));
    return y;
}
__device__ __forceinline__ void mma_f16(float* d, const uint32_t* a, const uint32_t* b) {
    asm volatile(
        "mma.sync.aligned.m16n8k16.row.col.f32.f16.f16.f32 "
        "{%0,%1,%2,%3}, {%4,%5,%6,%7}, {%8,%9}, {%0,%1,%2,%3};"
        : "+f"(d[0]), "+f"(d[1]), "+f"(d[2]), "+f"(d[3])
        : "r"(a[0]), "r"(a[1]), "r"(a[2]), "r"(a[3]), "r"(b[0]), "r"(b[1]));
}
__device__ __forceinline__ uint32_t packh2(float x, float y) {
    __half2 h = __floats2half2_rn(x, y);
    return *reinterpret_cast<uint32_t*>(&h);
}
__device__ __forceinline__ void ldmatrix_x4(uint32_t* r, const void* p) {
    uint32_t a = (uint32_t)__cvta_generic_to_shared(p);
    asm volatile("ldmatrix.sync.aligned.m8n8.x4.shared.b16 {%0,%1,%2,%3}, [%4];"
        : "=r"(r[0]), "=r"(r[1]), "=r"(r[2]), "=r"(r[3]) : "r"(a));
}
__device__ __forceinline__ void cp16(void* smem, const void* g) {
    uint32_t s = (uint32_t)__cvta_generic_to_shared(smem);
    asm volatile("cp.async.ca.shared.global [%0], [%1], 16;" :: "r"(s), "l"(g));
}
__device__ __forceinline__ void cp_commit() {
    asm volatile("cp.async.commit_group;");
}
template <int N>
__device__ __forceinline__ void cp_wait() {
    asm volatile("cp.async.wait_group %0;" :: "n"(N));
}

// ---------------------------------------------------------------------------
// Fused one-time formatting kernel (round-11, unchanged)
// ---------------------------------------------------------------------------
#define PREP_BLOCKS 18432

__global__ void __launch_bounds__(256) prep_kernel(
    const float* __restrict__ x,  const float* __restrict__ Wq,
    const float* __restrict__ Wk, const float* __restrict__ Wv,
    const float* __restrict__ Wo,
    __half* __restrict__ xh, __half* __restrict__ wqkT,
    __half* __restrict__ wvT, __half* __restrict__ woT)
{
    __shared__ float t[32][33];
    const int tid = threadIdx.x;
    int b = blockIdx.x;

    if (b < 8192) {
        int i = b * 256 + tid;
        float4 v = ((const float4*)x)[i];
        __half2 h0 = __floats2half2_rn(v.x, v.y);
        __half2 h1 = __floats2half2_rn(v.z, v.w);
        uint2 o;
        o.x = *reinterpret_cast<uint32_t*>(&h0);
        o.y = *reinterpret_cast<uint32_t*>(&h1);
        *(uint2*)(xh + 4 * (size_t)i) = o;
        return;
    }
    b -= 8192;

    const float* W;
    __half* Wt;
    int K, N;
    if (b < 4096)      { W = Wq; Wt = wqkT;                        K = D_IN; N = D_Q;  }
    else if (b < 5120) { b -= 4096; W = Wk; Wt = wqkT + (size_t)D_Q * D_IN; K = D_IN; N = D_KV; }
    else if (b < 6144) { b -= 5120; W = Wv; Wt = wvT;              K = D_IN; N = D_KV; }
    else               { b -= 6144; W = Wo; Wt = woT;              K = D_Q;  N = D_Q;  }

    const int nbx = N / 32;
    const int n0 = (b % nbx) * 32;
    const int k0 = (b / nbx) * 32;
    const int tx = tid & 31, ty = tid >> 5;

#pragma unroll
    for (int i = ty; i < 32; i += 8)
        t[i][tx] = W[(size_t)(k0 + i) * N + n0 + tx];
    __syncthreads();
#pragma unroll
    for (int i = ty; i < 32; i += 8)
        Wt[(size_t)(n0 + i) * K + k0 + tx] = __float2half_rn(t[tx][i]);
}

// ---------------------------------------------------------------------------
// fp16 tensor-core GEMM (round-12, byte-identical): 128x128 tile, BK=32,
// 3-stage cp.async, 128 threads / 4 warps, 64x64 warp tile.
// ---------------------------------------------------------------------------
template <int EPI>
__global__ void __launch_bounds__(128) gemm_h_kernel(
    const __half* __restrict__ A, const __half* __restrict__ Bt,
    const __half* __restrict__ A2,
    const float* __restrict__ bias, void* __restrict__ Cout,
    void* __restrict__ Cout2, void* __restrict__ Cout3,
    int N, int K)
{
    __shared__ __align__(16) __half As[3][128][40];
    __shared__ __align__(16) __half Bs[3][128][40];

    const int tid  = threadIdx.x;
    const int lane = tid & 31;
    const int wid  = tid >> 5;
    const int warpM = wid >> 1;
    const int warpN = wid & 1;
    const int bx = blockIdx.x, by = blockIdx.y;

    const __half *Ab, *Bb;
    __half* Ch = nullptr;
    float sc = 1.f;
    int ldO = 0, rowbase = 0, colbase = 0;
    if (EPI == 0) {
        Ab = A  + (size_t)(by * 128) * K;
        Bb = Bt + (size_t)(bx * 128) * K;
        rowbase = by * 128; colbase = bx * 128;
    } else {
        if (bx < 20) {
            Ab = A  + (size_t)(by * 128) * K;
            Bb = Bt + (size_t)(bx * 128) * K;
            rowbase = by * 128;
            if (bx < 16) { Ch = (__half*)Cout;  ldO = D_Q;  colbase = bx * 128;        sc = 0.125f; }
            else         { Ch = (__half*)Cout2; ldO = D_KV; colbase = (bx - 16) * 128; }
        } else {
            Ab = A2 + (size_t)((bx - 20) * 128) * K;
            Bb = A  + (size_t)(by * 128) * K;
            Ch = (__half*)Cout3; ldO = S_LEN;
            rowbase = (bx - 20) * 128; colbase = by * 128;
        }
    }

    float acc[4][8][4];
#pragma unroll
    for (int i = 0; i < 4; i++)
#pragma unroll
        for (int j = 0; j < 8; j++)
#pragma unroll
            for (int e = 0; e < 4; e++) acc[i][j][e] = 0.f;

    const int ldR = tid >> 2;
    const int ldC = (tid & 3) * 8;

    auto load_stage = [&](int s, int k0) {
#pragma unroll
        for (int i = 0; i < 4; i++) {
            cp16(&As[s][ldR + i * 32][ldC], Ab + (size_t)(ldR + i * 32) * K + k0 + ldC);
            cp16(&Bs[s][ldR + i * 32][ldC], Bb + (size_t)(ldR + i * 32) * K + k0 + ldC);
        }
    };

    const int nT = K / 32;
    load_stage(0, 0);  cp_commit();
    load_stage(1, 32); cp_commit();

    const int arow = warpM * 64 + (lane & 15);
    const int acolo = (lane >> 1) & 8;
    const int brow = warpN * 64 + (lane & 7) + ((lane & 16) >> 1);
    const int bcolo = lane & 8;

    for (int t = 0; t < nT; t++) {
        const int buf = t % 3;
        if (t + 2 < nT) {
            load_stage((t + 2) % 3, (t + 2) * 32);
            cp_commit();
            cp_wait<2>();
        } else {
            cp_wait<0>();
        }
        __syncthreads();

#pragma unroll
        for (int kk = 0; kk < 2; kk++) {
            uint32_t a[4][4], b[8][2];
            const int ac = kk * 16 + acolo;
            const int bc = kk * 16 + bcolo;
#pragma unroll
            for (int mi = 0; mi < 4; mi++)
                ldmatrix_x4(a[mi], &As[buf][arow + mi * 16][ac]);
#pragma unroll
            for (int np = 0; np < 4; np++) {
                uint32_t r[4];
                ldmatrix_x4(r, &Bs[buf][brow + np * 16][bc]);
                b[2 * np][0]     = r[0]; b[2 * np][1]     = r[1];
                b[2 * np + 1][0] = r[2]; b[2 * np + 1][1] = r[3];
            }
#pragma unroll
            for (int mi = 0; mi < 4; mi++)
#pragma unroll
                for (int ni = 0; ni < 8; ni++)
                    mma_f16(acc[mi][ni], a[mi], b[ni]);
        }
        __syncthreads();
    }

#pragma unroll
    for (int mi = 0; mi < 4; mi++) {
        int r = rowbase + warpM * 64 + mi * 16 + (lane >> 2);
#pragma unroll
        for (int ni = 0; ni < 8; ni++) {
            int c = colbase + warpN * 64 + ni * 8 + (lane & 3) * 2;
            if (EPI == 0) {
                float* C = (float*)Cout;
                float2 o0, o1;
                o0.x = acc[mi][ni][0] + bias[c]; o0.y = acc[mi][ni][1] + bias[c + 1];
                o1.x = acc[mi][ni][2] + bias[c]; o1.y = acc[mi][ni][3] + bias[c + 1];
                *(float2*)(C + (size_t)r * D_Q + c)       = o0;
                *(float2*)(C + (size_t)(r + 8) * D_Q + c) = o1;
            } else {
                *(__half2*)(Ch + (size_t)r * ldO + c) =
                    __floats2half2_rn(acc[mi][ni][0] * sc, acc[mi][ni][1] * sc);
                *(__half2*)(Ch + (size_t)(r + 8) * ldO + c) =
                    __floats2half2_rn(acc[mi][ni][2] * sc, acc[mi][ni][3] * sc);
            }
        }
    }
}

// ---------------------------------------------------------------------------
// Flash attention v2: 32 q-rows per warp (two m16 halves share every K/V
// B-fragment -> 0.25 ldmatrix/MMA, was 0.5). Zero-shift softmax p = exp(s),
// l via const ones-column MMA. Block: 128 threads / 4 warps = 2 heads x 64
// q-rows sharing one KV tile. Grid: (S/64 reversed, N_KV, 2 head-pairs).
// ---------------------------------------------------------------------------
__global__ void __launch_bounds__(128) flash_attn_tc_kernel(
    const __half* __restrict__ Qh, const __half* __restrict__ Kh,
    const __half* __restrict__ Vt, __half* __restrict__ O)
{
    __shared__ __align__(16) __half Ks[2][64][72];   // [j][d]
    __shared__ __align__(16) __half Vs[2][64][72];   // [d][j]

    const int qi  = (S_LEN / 64 - 1) - blockIdx.x;   // reversed for tail
    const int kvh = blockIdx.y;
    const int z   = blockIdx.z;
    const int tid = threadIdx.x;
    const int lane = tid & 31;
    const int w = tid >> 5;                          // 0..3
    const int h = kvh * 4 + z * 2 + (w >> 1);        // head
    const int qbase = qi * 64 + (w & 1) * 32;        // warp's first q row

    const float L2E = 1.44269504f;

    // Q fragments: two m16 halves (rows qbase..+15, qbase+16..+31)
    uint32_t qf0[4][4], qf1[4][4];
    {
        const size_t rg = (size_t)(qbase + (lane >> 2)) * D_Q + h * HDIM;
#pragma unroll
        for (int kk = 0; kk < 4; kk++) {
            int kc = kk * 16 + (lane & 3) * 2;
            qf0[kk][0] = *(const uint32_t*)(Qh + rg + kc);
            qf0[kk][1] = *(const uint32_t*)(Qh + rg + 8 * D_Q + kc);
            qf0[kk][2] = *(const uint32_t*)(Qh + rg + kc + 8);
            qf0[kk][3] = *(const uint32_t*)(Qh + rg + 8 * D_Q + kc + 8);
            qf1[kk][0] = *(const uint32_t*)(Qh + rg + 16 * D_Q + kc);
            qf1[kk][1] = *(const uint32_t*)(Qh + rg + 24 * D_Q + kc);
            qf1[kk][2] = *(const uint32_t*)(Qh + rg + 16 * D_Q + kc + 8);
            qf1[kk][3] = *(const uint32_t*)(Qh + rg + 24 * D_Q + kc + 8);
        }
    }

    // tile loader: 128 threads, 512 chunks per matrix -> 4 each
    const int ldJ = tid >> 1;            // 0..63
    const int ldC0 = (tid & 1) * 32;     // half-offset: chunks at +0/+32, two per row
    auto loadKV = [&](int s, int jt) {
#pragma unroll
        for (int i = 0; i < 2; i++) {
            int c = ldC0 + i * 8;        // halves 0,8 or 32,40 -> cover 0..63 with stride
            cp16(&Ks[s][ldJ][c],      Kh + (size_t)(jt * 64 + ldJ) * D_KV + kvh * HDIM + c);
            cp16(&Ks[s][ldJ][c + 16], Kh + (size_t)(jt * 64 + ldJ) * D_KV + kvh * HDIM + c + 16);
            cp16(&Vs[s][ldJ][c],      Vt + (size_t)(kvh * 64 + ldJ) * S_LEN + jt * 64 + c);
            cp16(&Vs[s][ldJ][c + 16], Vt + (size_t)(kvh * 64 + ldJ) * S_LEN + jt * 64 + c + 16);
        }
    };

    // constant ones-column B fragment (l accumulator tile)
    uint32_t bl[2];
    bl[0] = bl[1] = (lane < 4) ? 0x3C003C00u : 0u;

    const int mrow = (lane & 7) + ((lane & 16) >> 1);
    const int mcol = lane & 8;

    float o0[9][4], o1[9][4];
#pragma unroll
    for (int n8 = 0; n8 < 9; n8++)
#pragma unroll
        for (int e = 0; e < 4; e++) { o0[n8][e] = 0.f; o1[n8][e] = 0.f; }

    const int rq0 = qbase + (lane >> 2);  // half0 rows: rq0, rq0+8; half1: +16, +24
    const int nt = qi + 1;

    loadKV(0, 0);
    cp_commit();

    for (int jt = 0; jt < nt; jt++) {
        const int buf = jt & 1;
        if (jt + 1 < nt) {
            loadKV(buf ^ 1, jt + 1);
            cp_commit();
            cp_wait<1>();
        } else {
            cp_wait<0>();
        }
        __syncthreads();

        const int jb = jt * 64;
        const int jrel = qbase + 31 - jb;              // >= 31
        const int klim  = min(4, (jrel >> 4) + 1);     // PV k-steps
        const int nlim  = min(8, (jrel >> 3) + 1);     // QK n-tiles
        const int nlim2 = 2 * klim;
        const bool needMask = (jb + 63 > qbase);

        // ---- S = Q @ K^T : K fragment shared across both q halves ----
        float s0[8][4], s1[8][4];
#pragma unroll
        for (int n8 = 0; n8 < 8; n8++)
#pragma unroll
            for (int e = 0; e < 4; e++) { s0[n8][e] = 0.f; s1[n8][e] = 0.f; }

#pragma unroll
        for (int kk = 0; kk < 4; kk++) {
#pragma unroll
            for (int np = 0; np < 4; np++) {
                if (2 * np < nlim) {
                    uint32_t r[4];
                    ldmatrix_x4(r, &Ks[buf][np * 16 + mrow][kk * 16 + mcol]);
                    mma_f16(s0[2 * np], qf0[kk], r);
                    mma_f16(s1[2 * np], qf1[kk], r);
                    if (2 * np + 1 < nlim) {
                        mma_f16(s0[2 * np + 1], qf0[kk], r + 2);
                        mma_f16(s1[2 * np + 1], qf1[kk], r + 2);
                    }
                }
            }
        }

        // ---- causal mask (global indices) ----
        if (needMask) {
#pragma unroll
            for (int n8 = 0; n8 < 8; n8++) {
                if (n8 < nlim2) {
                    int j0 = jb + n8 * 8 + (lane & 3) * 2;
                    if (j0     > rq0)      s0[n8][0] = -INFINITY;
                    if (j0 + 1 > rq0)      s0[n8][1] = -INFINITY;
                    if (j0     > rq0 + 8)  s0[n8][2] = -INFINITY;
                    if (j0 + 1 > rq0 + 8)  s0[n8][3] = -INFINITY;
                    if (j0     > rq0 + 16) s1[n8][0] = -INFINITY;
                    if (j0 + 1 > rq0 + 16) s1[n8][1] = -INFINITY;
                    if (j0     > rq0 + 24) s1[n8][2] = -INFINITY;
                    if (j0 + 1 > rq0 + 24) s1[n8][3] = -INFINITY;
                }
            }
        }

        // ---- zero-shift exp ----
        uint32_t P01a[8], P23a[8], P01b[8], P23b[8];
#pragma unroll
        for (int n8 = 0; n8 < 8; n8++) {
            if (n8 < nlim2) {
                P01a[n8] = h2ex2(packh2(s0[n8][0] * L2E, s0[n8][1] * L2E));
                P23a[n8] = h2ex2(packh2(s0[n8][2] * L2E, s0[n8][3] * L2E));
                P01b[n8] = h2ex2(packh2(s1[n8][0] * L2E, s1[n8][1] * L2E));
                P23b[n8] = h2ex2(packh2(s1[n8][2] * L2E, s1[n8][3] * L2E));
            }
        }

        // ---- ctx += P @ V : V fragment shared across both q halves ----
#pragma unroll
        for (int kk = 0; kk < 4; kk++) {
            if (kk < klim) {
                uint32_t a0[4], a1[4];
                a0[0] = P01a[2 * kk];     a0[1] = P23a[2 * kk];
                a0[2] = P01a[2 * kk + 1]; a0[3] = P23a[2 * kk + 1];
                a1[0] = P01b[2 * kk];     a1[1] = P23b[2 * kk];
                a1[2] = P01b[2 * kk + 1]; a1[3] = P23b[2 * kk + 1];
#pragma unroll
                for (int np = 0; np < 4; np++) {
                    uint32_t r[4];
                    ldmatrix_x4(r, &Vs[buf][np * 16 + mrow][kk * 16 + mcol]);
                    mma_f16(o0[2 * np],     a0, r);
                    mma_f16(o1[2 * np],     a1, r);
                    mma_f16(o0[2 * np + 1], a0, r + 2);
                    mma_f16(o1[2 * np + 1], a1, r + 2);
                }
                mma_f16(o0[8], a0, bl);
                mma_f16(o1[8], a1, bl);
            }
        }
        __syncthreads();
    }

    // finalize: l in [8][0]/[8][2] of quad-leader lanes
    const float l00 = __shfl_sync(0xffffffff, o0[8][0], lane & 28);
    const float l01 = __shfl_sync(0xffffffff, o0[8][2], lane & 28);
    const float l10 = __shfl_sync(0xffffffff, o1[8][0], lane & 28);
    const float l11 = __shfl_sync(0xffffffff, o1[8][2], lane & 28);
    const float i00 = 1.f / l00, i01 = 1.f / l01;
    const float i10 = 1.f / l10, i11 = 1.f / l11;

#pragma unroll
    for (int n8 = 0; n8 < 8; n8++) {
        int col = h * HDIM + n8 * 8 + (lane & 3) * 2;
        *(__half2*)(O + (size_t)rq0 * D_Q + col) =
            __floats2half2_rn(o0[n8][0] * i00, o0[n8][1] * i00);
        *(__half2*)(O + (size_t)(rq0 + 8) * D_Q + col) =
            __floats2half2_rn(o0[n8][2] * i01, o0[n8][3] * i01);
        *(__half2*)(O + (size_t)(rq0 + 16) * D_Q + col) =
            __floats2half2_rn(o1[n8][0] * i10, o1[n8][1] * i10);
        *(__half2*)(O + (size_t)(rq0 + 24) * D_Q + col) =
            __floats2half2_rn(o1[n8][2] * i11, o1[n8][3] * i11);
    }
}

// ---------------------------------------------------------------------------
extern "C" void kernel_launch(void* const* d_in, const int* in_sizes, int n_in,
                              void* d_out, int out_size)
{
    const float* x  = (const float*)d_in[0];
    const float* Wq = (const float*)d_in[1];
    const float* Wk = (const float*)d_in[2];
    const float* Wv = (const float*)d_in[3];
    const float* Wo = (const float*)d_in[4];
    const float* bo = (const float*)d_in[5];
    float* out = (float*)d_out;

    __half *xh, *wqkT, *wvT, *woT, *qh, *kh, *vt, *ctx;
    cudaGetSymbolAddress((void**)&xh,   g_xh);
    cudaGetSymbolAddress((void**)&wqkT, g_wqkT);
    cudaGetSymbolAddress((void**)&wvT,  g_wvT);
    cudaGetSymbolAddress((void**)&woT,  g_woT);
    cudaGetSymbolAddress((void**)&qh,   g_qh);
    cudaGetSymbolAddress((void**)&kh,   g_kh);
    cudaGetSymbolAddress((void**)&vt,   g_vt);
    cudaGetSymbolAddress((void**)&ctx,  g_ctx);

    // one-time formatting: single fused launch
    prep_kernel<<<PREP_BLOCKS, 256>>>(x, Wq, Wk, Wv, Wo, xh, wqkT, wvT, woT);

    // merged Q | K | V^T projections
    gemm_h_kernel<3><<<dim3(24, 32), 128>>>(
        xh, wqkT, wvT, nullptr, qh, kh, vt, D_Q + D_KV, D_IN);

    // attention (GQA-shared KV tiles, 32 q-rows/warp)
    flash_attn_tc_kernel<<<dim3(S_LEN / 64, N_KV, 2), 128>>>(qh, kh, vt, ctx);

    // output projection + bias
    gemm_h_kernel<0><<<dim3(16, 32), 128>>>(
        ctx, woT, nullptr, bo, out, nullptr, nullptr, D_Q, D_IN);
}

// round 14
// speedup vs baseline: 1.1596x; 1.1596x over previous
#include <cuda_runtime.h>
#include <cuda_fp16.h>
#include <math.h>
#include <stdint.h>

#define S_LEN   4096
#define D_IN    2048
#define D_Q     2048
#define D_KV    512
#define N_HEADS 32
#define N_KV    8
#define HDIM    64

// Scratch (device globals: allocation-free per harness rules)
__device__ __half g_xh  [S_LEN * D_IN];          // x, fp16
__device__ __half g_wqkT[(D_Q + D_KV) * D_IN];   // [Wq^T ; Wk^T] fp16 [N][K]
__device__ __half g_wvT [D_KV * D_IN];
__device__ __half g_woT [D_Q  * D_Q];
__device__ __half g_qh  [S_LEN * D_Q];           // q fp16, pre-scaled 1/8
__device__ __half g_kh  [S_LEN * D_KV];          // k fp16
__device__ __half g_vt  [D_KV * S_LEN];          // v fp16 transposed [d][s]
__device__ __half g_ctx [S_LEN * D_Q];           // attention out fp16

// ---------------------------------------------------------------------------
// helpers
// ---------------------------------------------------------------------------
__device__ __forceinline__ uint32_t h2ex2(uint32_t x) {
    uint32_t y;
    asm("ex2.approx.f16x2 %0, %1;" : "=r"(y) : "r"(x));
    return y;
}
__device__ __forceinline__ void mma_f16(float* d, const uint32_t* a, const uint32_t* b) {
    asm volatile(
        "mma.sync.aligned.m16n8k16.row.col.f32.f16.f16.f32 "
        "{%0,%1,%2,%3}, {%4,%5,%6,%7}, {%8,%9}, {%0,%1,%2,%3};"
        : "+f"(d[0]), "+f"(d[1]), "+f"(d[2]), "+f"(d[3])
        : "r"(a[0]), "r"(a[1]), "r"(a[2]), "r"(a[3]), "r"(b[0]), "r"(b[1]));
}
__device__ __forceinline__ uint32_t packh2(float x, float y) {
    __half2 h = __floats2half2_rn(x, y);
    return *reinterpret_cast<uint32_t*>(&h);
}
__device__ __forceinline__ void ldmatrix_x4(uint32_t* r, const void* p) {
    uint32_t a = (uint32_t)__cvta_generic_to_shared(p);
    asm volatile("ldmatrix.sync.aligned.m8n8.x4.shared.b16 {%0,%1,%2,%3}, [%4];"
        : "=r"(r[0]), "=r"(r[1]), "=r"(r[2]), "=r"(r[3]) : "r"(a));
}
__device__ __forceinline__ void ldmatrix_x4_s(uint32_t* r, uint32_t a) {
    asm volatile("ldmatrix.sync.aligned.m8n8.x4.shared.b16 {%0,%1,%2,%3}, [%4];"
        : "=r"(r[0]), "=r"(r[1]), "=r"(r[2]), "=r"(r[3]) : "r"(a));
}
__device__ __forceinline__ void cp16(void* smem, const void* g) {
    uint32_t s = (uint32_t)__cvta_generic_to_shared(smem);
    asm volatile("cp.async.ca.shared.global [%0], [%1], 16;" :: "r"(s), "l"(g));
}
__device__ __forceinline__ void cp16s(uint32_t s, const void* g) {
    asm volatile("cp.async.ca.shared.global [%0], [%1], 16;" :: "r"(s), "l"(g));
}
__device__ __forceinline__ void cp_commit() {
    asm volatile("cp.async.commit_group;");
}
template <int N>
__device__ __forceinline__ void cp_wait() {
    asm volatile("cp.async.wait_group %0;" :: "n"(N));
}

// ---------------------------------------------------------------------------
// Fused one-time formatting kernel (round-11, unchanged)
// ---------------------------------------------------------------------------
#define PREP_BLOCKS 18432

__global__ void __launch_bounds__(256) prep_kernel(
    const float* __restrict__ x,  const float* __restrict__ Wq,
    const float* __restrict__ Wk, const float* __restrict__ Wv,
    const float* __restrict__ Wo,
    __half* __restrict__ xh, __half* __restrict__ wqkT,
    __half* __restrict__ wvT, __half* __restrict__ woT)
{
    __shared__ float t[32][33];
    const int tid = threadIdx.x;
    int b = blockIdx.x;

    if (b < 8192) {
        int i = b * 256 + tid;
        float4 v = ((const float4*)x)[i];
        __half2 h0 = __floats2half2_rn(v.x, v.y);
        __half2 h1 = __floats2half2_rn(v.z, v.w);
        uint2 o;
        o.x = *reinterpret_cast<uint32_t*>(&h0);
        o.y = *reinterpret_cast<uint32_t*>(&h1);
        *(uint2*)(xh + 4 * (size_t)i) = o;
        return;
    }
    b -= 8192;

    const float* W;
    __half* Wt;
    int K, N;
    if (b < 4096)      { W = Wq; Wt = wqkT;                        K = D_IN; N = D_Q;  }
    else if (b < 5120) { b -= 4096; W = Wk; Wt = wqkT + (size_t)D_Q * D_IN; K = D_IN; N = D_KV; }
    else if (b < 6144) { b -= 5120; W = Wv; Wt = wvT;              K = D_IN; N = D_KV; }
    else               { b -= 6144; W = Wo; Wt = woT;              K = D_Q;  N = D_Q;  }

    const int nbx = N / 32;
    const int n0 = (b % nbx) * 32;
    const int k0 = (b / nbx) * 32;
    const int tx = tid & 31, ty = tid >> 5;

#pragma unroll
    for (int i = ty; i < 32; i += 8)
        t[i][tx] = W[(size_t)(k0 + i) * N + n0 + tx];
    __syncthreads();
#pragma unroll
    for (int i = ty; i < 32; i += 8)
        Wt[(size_t)(n0 + i) * K + k0 + tx] = __float2half_rn(t[tx][i]);
}

// ---------------------------------------------------------------------------
// fp16 tensor-core GEMM: 128x128 tile, BK=32, 128 threads / 4 warps,
// 64x64 warp tile. *** 4-stage cp.async ring, ONE __syncthreads/iter ***
// (load(t+3) issued after the top barrier targets stage (t-1)&3, which all
//  warps finished reading in iter t-1 — prefetch depth stays 3).
// EPI 0: Wo GEMM -> fp32 + bias (grid 16x32).
// EPI 3: merged QKV (grid 24x32): bx<16 Q | 16-19 K | 20-23 V^T.
// ---------------------------------------------------------------------------
#define GS_STAGE 20480                  // (128 rows * 80B) * 2 matrices
#define GS_SMEM  (4 * GS_STAGE)         // 81920 B dynamic

template <int EPI>
__global__ void __launch_bounds__(128) gemm_h_kernel(
    const __half* __restrict__ A, const __half* __restrict__ Bt,
    const __half* __restrict__ A2,
    const float* __restrict__ bias, void* __restrict__ Cout,
    void* __restrict__ Cout2, void* __restrict__ Cout3,
    int N, int K)
{
    extern __shared__ __align__(16) char dsm[];
    const uint32_t sb = (uint32_t)__cvta_generic_to_shared(dsm);

    const int tid  = threadIdx.x;
    const int lane = tid & 31;
    const int wid  = tid >> 5;
    const int warpM = wid >> 1;
    const int warpN = wid & 1;
    const int bx = blockIdx.x, by = blockIdx.y;

    const __half *Ab, *Bb;
    __half* Ch = nullptr;
    float sc = 1.f;
    int ldO = 0, rowbase = 0, colbase = 0;
    if (EPI == 0) {
        Ab = A  + (size_t)(by * 128) * K;
        Bb = Bt + (size_t)(bx * 128) * K;
        rowbase = by * 128; colbase = bx * 128;
    } else {
        if (bx < 20) {
            Ab = A  + (size_t)(by * 128) * K;
            Bb = Bt + (size_t)(bx * 128) * K;
            rowbase = by * 128;
            if (bx < 16) { Ch = (__half*)Cout;  ldO = D_Q;  colbase = bx * 128;        sc = 0.125f; }
            else         { Ch = (__half*)Cout2; ldO = D_KV; colbase = (bx - 16) * 128; }
        } else {
            Ab = A2 + (size_t)((bx - 20) * 128) * K;
            Bb = A  + (size_t)(by * 128) * K;
            Ch = (__half*)Cout3; ldO = S_LEN;
            rowbase = (bx - 20) * 128; colbase = by * 128;
        }
    }

    float acc[4][8][4];
#pragma unroll
    for (int i = 0; i < 4; i++)
#pragma unroll
        for (int j = 0; j < 8; j++)
#pragma unroll
            for (int e = 0; e < 4; e++) acc[i][j][e] = 0.f;

    const int ldR = tid >> 2;            // 0..31
    const int ldC = (tid & 3) * 8;       // half offset

    auto load_stage = [&](int s, int k0) {
        const uint32_t ta = sb + s * GS_STAGE;
        const uint32_t tb = ta + 10240;
#pragma unroll
        for (int i = 0; i < 4; i++) {
            const int r = ldR + i * 32;
            cp16s(ta + r * 80 + ldC * 2, Ab + (size_t)r * K + k0 + ldC);
            cp16s(tb + r * 80 + ldC * 2, Bb + (size_t)r * K + k0 + ldC);
        }
    };

    const int nT = K / 32;
    load_stage(0, 0);  cp_commit();
    load_stage(1, 32); cp_commit();
    load_stage(2, 64); cp_commit();

    const int arow = warpM * 64 + (lane & 15);
    const int acolo = (lane >> 1) & 8;
    const int brow = warpN * 64 + (lane & 7) + ((lane & 16) >> 1);
    const int bcolo = lane & 8;

    for (int t = 0; t < nT; t++) {
        cp_wait<2>();
        __syncthreads();
        if (t + 3 < nT) load_stage((t + 3) & 3, (t + 3) * 32);
        cp_commit();                     // one group per iteration (may be empty)

        const uint32_t ta = sb + (t & 3) * GS_STAGE;
        const uint32_t tb = ta + 10240;
#pragma unroll
        for (int kk = 0; kk < 2; kk++) {
            uint32_t a[4][4], b[8][2];
            const int ac = kk * 16 + acolo;
            const int bc = kk * 16 + bcolo;
#pragma unroll
            for (int mi = 0; mi < 4; mi++)
                ldmatrix_x4_s(a[mi], ta + (arow + mi * 16) * 80 + ac * 2);
#pragma unroll
            for (int np = 0; np < 4; np++) {
                uint32_t r[4];
                ldmatrix_x4_s(r, tb + (brow + np * 16) * 80 + bc * 2);
                b[2 * np][0]     = r[0]; b[2 * np][1]     = r[1];
                b[2 * np + 1][0] = r[2]; b[2 * np + 1][1] = r[3];
            }
#pragma unroll
            for (int mi = 0; mi < 4; mi++)
#pragma unroll
                for (int ni = 0; ni < 8; ni++)
                    mma_f16(acc[mi][ni], a[mi], b[ni]);
        }
    }

    // epilogue: 64x64 per warp
#pragma unroll
    for (int mi = 0; mi < 4; mi++) {
        int r = rowbase + warpM * 64 + mi * 16 + (lane >> 2);
#pragma unroll
        for (int ni = 0; ni < 8; ni++) {
            int c = colbase + warpN * 64 + ni * 8 + (lane & 3) * 2;
            if (EPI == 0) {
                float* C = (float*)Cout;
                float2 o0, o1;
                o0.x = acc[mi][ni][0] + bias[c]; o0.y = acc[mi][ni][1] + bias[c + 1];
                o1.x = acc[mi][ni][2] + bias[c]; o1.y = acc[mi][ni][3] + bias[c + 1];
                *(float2*)(C + (size_t)r * D_Q + c)       = o0;
                *(float2*)(C + (size_t)(r + 8) * D_Q + c) = o1;
            } else {
                *(__half2*)(Ch + (size_t)r * ldO + c) =
                    __floats2half2_rn(acc[mi][ni][0] * sc, acc[mi][ni][1] * sc);
                *(__half2*)(Ch + (size_t)(r + 8) * ldO + c) =
                    __floats2half2_rn(acc[mi][ni][2] * sc, acc[mi][ni][3] * sc);
            }
        }
    }
}

// ---------------------------------------------------------------------------
// Flash attention (round-12 version, byte-identical): causal GQA-shared KV,
// zero-shift softmax p = exp(s), l via const ones-column MMA.
// Block: 256 threads (8 warps) = 4 heads x 32 q-rows sharing one K/V tile.
// Grid: (S/32 reversed, N_KV).
// ---------------------------------------------------------------------------
__global__ void __launch_bounds__(256) flash_attn_tc_kernel(
    const __half* __restrict__ Qh, const __half* __restrict__ Kh,
    const __half* __restrict__ Vt, __half* __restrict__ O)
{
    __shared__ __align__(16) __half Ks[2][64][72];   // [j][d]
    __shared__ __align__(16) __half Vs[2][64][72];   // [d][j]

    const int qi  = (S_LEN / 32 - 1) - blockIdx.x;   // reversed for tail
    const int kvh = blockIdx.y;
    const int tid = threadIdx.x;
    const int lane = tid & 31;
    const int w = tid >> 5;
    const int h = kvh * 4 + (w >> 1);
    const int qbase = qi * 32 + (w & 1) * 16;

    const float L2E = 1.44269504f;

    // Q fragments from global (fp16, pre-scaled 1/8)
    uint32_t qf[4][4];
    {
        const size_t r0g = (size_t)(qbase + (lane >> 2)) * D_Q + h * HDIM;
#pragma unroll
        for (int kk = 0; kk < 4; kk++) {
            int kc = kk * 16 + (lane & 3) * 2;
            qf[kk][0] = *(const uint32_t*)(Qh + r0g + kc);
            qf[kk][1] = *(const uint32_t*)(Qh + r0g + 8 * D_Q + kc);
            qf[kk][2] = *(const uint32_t*)(Qh + r0g + kc + 8);
            qf[kk][3] = *(const uint32_t*)(Qh + r0g + 8 * D_Q + kc + 8);
        }
    }

    const int ldJ = tid >> 3;
    const int ldC = (tid & 7) * 8;
    auto loadKV = [&](int s, int jt) {
#pragma unroll
        for (int i = 0; i < 2; i++) {
            int j = ldJ + i * 32;
            cp16(&Ks[s][j][ldC], Kh + (size_t)(jt * 64 + j) * D_KV + kvh * HDIM + ldC);
            cp16(&Vs[s][j][ldC], Vt + (size_t)(kvh * 64 + j) * S_LEN + jt * 64 + ldC);
        }
    };

    // constant ones-column B fragment (l accumulator tile)
    uint32_t bl[2];
    bl[0] = bl[1] = (lane < 4) ? 0x3C003C00u : 0u;

    const int mrow = (lane & 7) + ((lane & 16) >> 1);
    const int mcol = lane & 8;

    float o[9][4];                        // [0..7]=ctx, [8]=l column
#pragma unroll
    for (int n8 = 0; n8 < 9; n8++)
#pragma unroll
        for (int e = 0; e < 4; e++) o[n8][e] = 0.f;

    const int rq0 = qbase + (lane >> 2);
    const int nt = qi / 2 + 1;

    loadKV(0, 0);
    cp_commit();

    for (int jt = 0; jt < nt; jt++) {
        const int buf = jt & 1;
        if (jt + 1 < nt) {
            loadKV(buf ^ 1, jt + 1);
            cp_commit();
            cp_wait<1>();
        } else {
            cp_wait<0>();
        }
        __syncthreads();

        const int jb = jt * 64;
        const int jrel = qbase + 15 - jb;
        const int klim  = min(4, (jrel >> 4) + 1);
        const int nlim  = min(8, (jrel >> 3) + 1);
        const int nlim2 = 2 * klim;
        const bool needMask = (jb + 63 > qbase);

        // ---- S = Q @ K^T ----
        float s[8][4];
#pragma unroll
        for (int n8 = 0; n8 < 8; n8++)
#pragma unroll
            for (int e = 0; e < 4; e++) s[n8][e] = 0.f;

#pragma unroll
        for (int kk = 0; kk < 4; kk++) {
#pragma unroll
            for (int np = 0; np < 4; np++) {
                if (2 * np < nlim) {
                    uint32_t r[4];
                    ldmatrix_x4(r, &Ks[buf][np * 16 + mrow][kk * 16 + mcol]);
                    mma_f16(s[2 * np], qf[kk], r);
                    if (2 * np + 1 < nlim) mma_f16(s[2 * np + 1], qf[kk], r + 2);
                }
            }
        }

        // ---- causal mask ----
        if (needMask) {
#pragma unroll
            for (int n8 = 0; n8 < 8; n8++) {
                if (n8 < nlim2) {
                    int j0 = jb + n8 * 8 + (lane & 3) * 2;
                    if (j0     > rq0)     s[n8][0] = -INFINITY;
                    if (j0 + 1 > rq0)     s[n8][1] = -INFINITY;
                    if (j0     > rq0 + 8) s[n8][2] = -INFINITY;
                    if (j0 + 1 > rq0 + 8) s[n8][3] = -INFINITY;
                }
            }
        }

        // ---- zero-shift exp (no reductions, no rescale) ----
        uint32_t P01[8], P23[8];
#pragma unroll
        for (int n8 = 0; n8 < 8; n8++) {
            if (n8 < nlim2) {
                P01[n8] = h2ex2(packh2(s[n8][0] * L2E, s[n8][1] * L2E));
                P23[n8] = h2ex2(packh2(s[n8][2] * L2E, s[n8][3] * L2E));
            }
        }

        // ---- ctx += P @ V (+ l via ones column) ----
#pragma unroll
        for (int kk = 0; kk < 4; kk++) {
            if (kk < klim) {
                uint32_t a[4];
                a[0] = P01[2 * kk];     a[1] = P23[2 * kk];
                a[2] = P01[2 * kk + 1]; a[3] = P23[2 * kk + 1];
#pragma unroll
                for (int np = 0; np < 4; np++) {
                    uint32_t r[4];
                    ldmatrix_x4(r, &Vs[buf][np * 16 + mrow][kk * 16 + mcol]);
                    mma_f16(o[2 * np],     a, r);
                    mma_f16(o[2 * np + 1], a, r + 2);
                }
                mma_f16(o[8], a, bl);
            }
        }
        __syncthreads();
    }

    // finalize: l in o[8][0]/o[8][2] of quad-leader lanes
    const float l0 = __shfl_sync(0xffffffff, o[8][0], lane & 28);
    const float l1 = __shfl_sync(0xffffffff, o[8][2], lane & 28);
    const float i0 = 1.f / l0;
    const float i1 = 1.f / l1;

#pragma unroll
    for (int n8 = 0; n8 < 8; n8++) {
        int col = h * HDIM + n8 * 8 + (lane & 3) * 2;
        *(__half2*)(O + (size_t)rq0 * D_Q + col) =
            __floats2half2_rn(o[n8][0] * i0, o[n8][1] * i0);
        *(__half2*)(O + (size_t)(rq0 + 8) * D_Q + col) =
            __floats2half2_rn(o[n8][2] * i1, o[n8][3] * i1);
    }
}

// ---------------------------------------------------------------------------
extern "C" void kernel_launch(void* const* d_in, const int* in_sizes, int n_in,
                              void* d_out, int out_size)
{
    const float* x  = (const float*)d_in[0];
    const float* Wq = (const float*)d_in[1];
    const float* Wk = (const float*)d_in[2];
    const float* Wv = (const float*)d_in[3];
    const float* Wo = (const float*)d_in[4];
    const float* bo = (const float*)d_in[5];
    float* out = (float*)d_out;

    __half *xh, *wqkT, *wvT, *woT, *qh, *kh, *vt, *ctx;
    cudaGetSymbolAddress((void**)&xh,   g_xh);
    cudaGetSymbolAddress((void**)&wqkT, g_wqkT);
    cudaGetSymbolAddress((void**)&wvT,  g_wvT);
    cudaGetSymbolAddress((void**)&woT,  g_woT);
    cudaGetSymbolAddress((void**)&qh,   g_qh);
    cudaGetSymbolAddress((void**)&kh,   g_kh);
    cudaGetSymbolAddress((void**)&vt,   g_vt);
    cudaGetSymbolAddress((void**)&ctx,  g_ctx);

    cudaFuncSetAttribute(gemm_h_kernel<0>, cudaFuncAttributeMaxDynamicSharedMemorySize, GS_SMEM);
    cudaFuncSetAttribute(gemm_h_kernel<3>, cudaFuncAttributeMaxDynamicSharedMemorySize, GS_SMEM);

    // one-time formatting: single fused launch
    prep_kernel<<<PREP_BLOCKS, 256>>>(x, Wq, Wk, Wv, Wo, xh, wqkT, wvT, woT);

    // merged Q | K | V^T projections
    gemm_h_kernel<3><<<dim3(24, 32), 128, GS_SMEM>>>(
        xh, wqkT, wvT, nullptr, qh, kh, vt, D_Q + D_KV, D_IN);

    // attention (GQA-shared KV tiles, zero-shift softmax)
    flash_attn_tc_kernel<<<dim3(S_LEN / 32, N_KV), 256>>>(qh, kh, vt, ctx);

    // output projection + bias
    gemm_h_kernel<0><<<dim3(16, 32), 128, GS_SMEM>>>(
        ctx, woT, nullptr, bo, out, nullptr, nullptr, D_Q, D_IN);
}

// round 15
// speedup vs baseline: 1.2299x; 1.0606x over previous
#include <cuda_runtime.h>
#include <cuda_fp16.h>
#include <math.h>
#include <stdint.h>

#define S_LEN   4096
#define D_IN    2048
#define D_Q     2048
#define D_KV    512
#define N_HEADS 32
#define N_KV    8
#define HDIM    64

// Scratch (device globals: allocation-free per harness rules)
__device__ __half g_xh  [S_LEN * D_IN];          // x, fp16
__device__ __half g_wqkT[(D_Q + D_KV) * D_IN];   // [Wq^T ; Wk^T] fp16 [N][K]
__device__ __half g_wvT [D_KV * D_IN];
__device__ __half g_woT [D_Q  * D_Q];
__device__ __half g_qh  [S_LEN * D_Q];           // q fp16, pre-scaled 1/8
__device__ __half g_kh  [S_LEN * D_KV];          // k fp16
__device__ __half g_vt  [D_KV * S_LEN];          // v fp16 transposed [d][s]
__device__ __half g_ctx [S_LEN * D_Q];           // attention out fp16

// ---------------------------------------------------------------------------
// helpers
// ---------------------------------------------------------------------------
__device__ __forceinline__ uint32_t h2ex2(uint32_t x) {
    uint32_t y;
    asm("ex2.approx.f16x2 %0, %1;" : "=r"(y) : "r"(x));
    return y;
}
__device__ __forceinline__ void mma_f16(float* d, const uint32_t* a, const uint32_t* b) {
    asm volatile(
        "mma.sync.aligned.m16n8k16.row.col.f32.f16.f16.f32 "
        "{%0,%1,%2,%3}, {%4,%5,%6,%7}, {%8,%9}, {%0,%1,%2,%3};"
        : "+f"(d[0]), "+f"(d[1]), "+f"(d[2]), "+f"(d[3])
        : "r"(a[0]), "r"(a[1]), "r"(a[2]), "r"(a[3]), "r"(b[0]), "r"(b[1]));
}
__device__ __forceinline__ uint32_t packh2(float x, float y) {
    __half2 h = __floats2half2_rn(x, y);
    return *reinterpret_cast<uint32_t*>(&h);
}
__device__ __forceinline__ void ldmatrix_x4(uint32_t* r, const void* p) {
    uint32_t a = (uint32_t)__cvta_generic_to_shared(p);
    asm volatile("ldmatrix.sync.aligned.m8n8.x4.shared.b16 {%0,%1,%2,%3}, [%4];"
        : "=r"(r[0]), "=r"(r[1]), "=r"(r[2]), "=r"(r[3]) : "r"(a));
}
__device__ __forceinline__ void cp16(void* smem, const void* g) {
    uint32_t s = (uint32_t)__cvta_generic_to_shared(smem);
    asm volatile("cp.async.ca.shared.global [%0], [%1], 16;" :: "r"(s), "l"(g));
}
__device__ __forceinline__ void cp_commit() {
    asm volatile("cp.async.commit_group;");
}
template <int N>
__device__ __forceinline__ void cp_wait() {
    asm volatile("cp.async.wait_group %0;" :: "n"(N));
}

// ---------------------------------------------------------------------------
// Fused one-time formatting kernel (round-11, unchanged)
// ---------------------------------------------------------------------------
#define PREP_BLOCKS 18432

__global__ void __launch_bounds__(256) prep_kernel(
    const float* __restrict__ x,  const float* __restrict__ Wq,
    const float* __restrict__ Wk, const float* __restrict__ Wv,
    const float* __restrict__ Wo,
    __half* __restrict__ xh, __half* __restrict__ wqkT,
    __half* __restrict__ wvT, __half* __restrict__ woT)
{
    __shared__ float t[32][33];
    const int tid = threadIdx.x;
    int b = blockIdx.x;

    if (b < 8192) {
        int i = b * 256 + tid;
        float4 v = ((const float4*)x)[i];
        __half2 h0 = __floats2half2_rn(v.x, v.y);
        __half2 h1 = __floats2half2_rn(v.z, v.w);
        uint2 o;
        o.x = *reinterpret_cast<uint32_t*>(&h0);
        o.y = *reinterpret_cast<uint32_t*>(&h1);
        *(uint2*)(xh + 4 * (size_t)i) = o;
        return;
    }
    b -= 8192;

    const float* W;
    __half* Wt;
    int K, N;
    if (b < 4096)      { W = Wq; Wt = wqkT;                        K = D_IN; N = D_Q;  }
    else if (b < 5120) { b -= 4096; W = Wk; Wt = wqkT + (size_t)D_Q * D_IN; K = D_IN; N = D_KV; }
    else if (b < 6144) { b -= 5120; W = Wv; Wt = wvT;              K = D_IN; N = D_KV; }
    else               { b -= 6144; W = Wo; Wt = woT;              K = D_Q;  N = D_Q;  }

    const int nbx = N / 32;
    const int n0 = (b % nbx) * 32;
    const int k0 = (b / nbx) * 32;
    const int tx = tid & 31, ty = tid >> 5;

#pragma unroll
    for (int i = ty; i < 32; i += 8)
        t[i][tx] = W[(size_t)(k0 + i) * N + n0 + tx];
    __syncthreads();
#pragma unroll
    for (int i = ty; i < 32; i += 8)
        Wt[(size_t)(n0 + i) * K + k0 + tx] = __float2half_rn(t[tx][i]);
}

// ---------------------------------------------------------------------------
// fp16 tensor-core GEMM (round-12 exact): 128x128 tile, BK=32, 3-stage
// cp.async, 128 threads / 4 warps, 64x64 warp tile.
// EPI 0: Wo GEMM -> fp32 + bias (grid 16x32).
// EPI 3: merged QKV (grid 24x32): bx<16 Q | 16-19 K | 20-23 V^T.
// ---------------------------------------------------------------------------
template <int EPI>
__global__ void __launch_bounds__(128) gemm_h_kernel(
    const __half* __restrict__ A, const __half* __restrict__ Bt,
    const __half* __restrict__ A2,
    const float* __restrict__ bias, void* __restrict__ Cout,
    void* __restrict__ Cout2, void* __restrict__ Cout3,
    int N, int K)
{
    __shared__ __align__(16) __half As[3][128][40];
    __shared__ __align__(16) __half Bs[3][128][40];

    const int tid  = threadIdx.x;
    const int lane = tid & 31;
    const int wid  = tid >> 5;
    const int warpM = wid >> 1;
    const int warpN = wid & 1;
    const int bx = blockIdx.x, by = blockIdx.y;

    const __half *Ab, *Bb;
    __half* Ch = nullptr;
    float sc = 1.f;
    int ldO = 0, rowbase = 0, colbase = 0;
    if (EPI == 0) {
        Ab = A  + (size_t)(by * 128) * K;
        Bb = Bt + (size_t)(bx * 128) * K;
        rowbase = by * 128; colbase = bx * 128;
    } else {
        if (bx < 20) {
            Ab = A  + (size_t)(by * 128) * K;
            Bb = Bt + (size_t)(bx * 128) * K;
            rowbase = by * 128;
            if (bx < 16) { Ch = (__half*)Cout;  ldO = D_Q;  colbase = bx * 128;        sc = 0.125f; }
            else         { Ch = (__half*)Cout2; ldO = D_KV; colbase = (bx - 16) * 128; }
        } else {
            Ab = A2 + (size_t)((bx - 20) * 128) * K;
            Bb = A  + (size_t)(by * 128) * K;
            Ch = (__half*)Cout3; ldO = S_LEN;
            rowbase = (bx - 20) * 128; colbase = by * 128;
        }
    }

    float acc[4][8][4];
#pragma unroll
    for (int i = 0; i < 4; i++)
#pragma unroll
        for (int j = 0; j < 8; j++)
#pragma unroll
            for (int e = 0; e < 4; e++) acc[i][j][e] = 0.f;

    const int ldR = tid >> 2;
    const int ldC = (tid & 3) * 8;

    auto load_stage = [&](int s, int k0) {
#pragma unroll
        for (int i = 0; i < 4; i++) {
            cp16(&As[s][ldR + i * 32][ldC], Ab + (size_t)(ldR + i * 32) * K + k0 + ldC);
            cp16(&Bs[s][ldR + i * 32][ldC], Bb + (size_t)(ldR + i * 32) * K + k0 + ldC);
        }
    };

    const int nT = K / 32;
    load_stage(0, 0);  cp_commit();
    load_stage(1, 32); cp_commit();

    const int arow = warpM * 64 + (lane & 15);
    const int acolo = (lane >> 1) & 8;
    const int brow = warpN * 64 + (lane & 7) + ((lane & 16) >> 1);
    const int bcolo = lane & 8;

    for (int t = 0; t < nT; t++) {
        const int buf = t % 3;
        if (t + 2 < nT) {
            load_stage((t + 2) % 3, (t + 2) * 32);
            cp_commit();
            cp_wait<2>();
        } else {
            cp_wait<0>();
        }
        __syncthreads();

#pragma unroll
        for (int kk = 0; kk < 2; kk++) {
            uint32_t a[4][4], b[8][2];
            const int ac = kk * 16 + acolo;
            const int bc = kk * 16 + bcolo;
#pragma unroll
            for (int mi = 0; mi < 4; mi++)
                ldmatrix_x4(a[mi], &As[buf][arow + mi * 16][ac]);
#pragma unroll
            for (int np = 0; np < 4; np++) {
                uint32_t r[4];
                ldmatrix_x4(r, &Bs[buf][brow + np * 16][bc]);
                b[2 * np][0]     = r[0]; b[2 * np][1]     = r[1];
                b[2 * np + 1][0] = r[2]; b[2 * np + 1][1] = r[3];
            }
#pragma unroll
            for (int mi = 0; mi < 4; mi++)
#pragma unroll
                for (int ni = 0; ni < 8; ni++)
                    mma_f16(acc[mi][ni], a[mi], b[ni]);
        }
        __syncthreads();
    }

#pragma unroll
    for (int mi = 0; mi < 4; mi++) {
        int r = rowbase + warpM * 64 + mi * 16 + (lane >> 2);
#pragma unroll
        for (int ni = 0; ni < 8; ni++) {
            int c = colbase + warpN * 64 + ni * 8 + (lane & 3) * 2;
            if (EPI == 0) {
                float* C = (float*)Cout;
                float2 o0, o1;
                o0.x = acc[mi][ni][0] + bias[c]; o0.y = acc[mi][ni][1] + bias[c + 1];
                o1.x = acc[mi][ni][2] + bias[c]; o1.y = acc[mi][ni][3] + bias[c + 1];
                *(float2*)(C + (size_t)r * D_Q + c)       = o0;
                *(float2*)(C + (size_t)(r + 8) * D_Q + c) = o1;
            } else {
                *(__half2*)(Ch + (size_t)r * ldO + c) =
                    __floats2half2_rn(acc[mi][ni][0] * sc, acc[mi][ni][1] * sc);
                *(__half2*)(Ch + (size_t)(r + 8) * ldO + c) =
                    __floats2half2_rn(acc[mi][ni][2] * sc, acc[mi][ni][3] * sc);
            }
        }
    }
}

// ---------------------------------------------------------------------------
// Flash attention v3: 32 q-rows per warp, KV tile processed in TWO 32-column
// groups (QK -> mask -> exp -> PV per group) to cap live registers (~180).
// Every K/V B-fragment serves both q-halves: 0.235 ldmatrix/MMA (was 0.47).
// Zero-shift softmax p = exp(s); l via const ones-column MMA.
// Block: 128 threads / 4 warps = 2 heads x 64 q-rows sharing one KV tile.
// Grid: (S/64 reversed, N_KV, 2 head-pairs).
// ---------------------------------------------------------------------------
__global__ void __launch_bounds__(128) flash_attn_tc_kernel(
    const __half* __restrict__ Qh, const __half* __restrict__ Kh,
    const __half* __restrict__ Vt, __half* __restrict__ O)
{
    __shared__ __align__(16) __half Ks[2][64][72];   // [j][d]
    __shared__ __align__(16) __half Vs[2][64][72];   // [d][j]

    const int qi  = (S_LEN / 64 - 1) - blockIdx.x;   // reversed for tail
    const int kvh = blockIdx.y;
    const int z   = blockIdx.z;
    const int tid = threadIdx.x;
    const int lane = tid & 31;
    const int w = tid >> 5;
    const int h = kvh * 4 + z * 2 + (w >> 1);
    const int qbase = qi * 64 + (w & 1) * 32;        // warp's first q row

    const float L2E = 1.44269504f;

    // Q fragments: two m16 halves (rows qbase..+15, +16..+31)
    uint32_t qf0[4][4], qf1[4][4];
    {
        const size_t rg = (size_t)(qbase + (lane >> 2)) * D_Q + h * HDIM;
#pragma unroll
        for (int kk = 0; kk < 4; kk++) {
            int kc = kk * 16 + (lane & 3) * 2;
            qf0[kk][0] = *(const uint32_t*)(Qh + rg + kc);
            qf0[kk][1] = *(const uint32_t*)(Qh + rg + 8 * D_Q + kc);
            qf0[kk][2] = *(const uint32_t*)(Qh + rg + kc + 8);
            qf0[kk][3] = *(const uint32_t*)(Qh + rg + 8 * D_Q + kc + 8);
            qf1[kk][0] = *(const uint32_t*)(Qh + rg + 16 * D_Q + kc);
            qf1[kk][1] = *(const uint32_t*)(Qh + rg + 24 * D_Q + kc);
            qf1[kk][2] = *(const uint32_t*)(Qh + rg + 16 * D_Q + kc + 8);
            qf1[kk][3] = *(const uint32_t*)(Qh + rg + 24 * D_Q + kc + 8);
        }
    }

    // tile loader: 128 threads x 4 cp16 per matrix
    const int ldJ = tid >> 1;            // 0..63
    const int ldC0 = (tid & 1) * 32;
    auto loadKV = [&](int s, int jt) {
#pragma unroll
        for (int i = 0; i < 2; i++) {
            int c = ldC0 + i * 8;
            cp16(&Ks[s][ldJ][c],      Kh + (size_t)(jt * 64 + ldJ) * D_KV + kvh * HDIM + c);
            cp16(&Ks[s][ldJ][c + 16], Kh + (size_t)(jt * 64 + ldJ) * D_KV + kvh * HDIM + c + 16);
            cp16(&Vs[s][ldJ][c],      Vt + (size_t)(kvh * 64 + ldJ) * S_LEN + jt * 64 + c);
            cp16(&Vs[s][ldJ][c + 16], Vt + (size_t)(kvh * 64 + ldJ) * S_LEN + jt * 64 + c + 16);
        }
    };

    // constant ones-column B fragment (l accumulator tile)
    uint32_t bl[2];
    bl[0] = bl[1] = (lane < 4) ? 0x3C003C00u : 0u;

    const int mrow = (lane & 7) + ((lane & 16) >> 1);
    const int mcol = lane & 8;

    float o0[9][4], o1[9][4];
#pragma unroll
    for (int n8 = 0; n8 < 9; n8++)
#pragma unroll
        for (int e = 0; e < 4; e++) { o0[n8][e] = 0.f; o1[n8][e] = 0.f; }

    const int rq0 = qbase + (lane >> 2);  // half0 rows: rq0, rq0+8; half1: +16, +24
    const int nt = qi + 1;

    loadKV(0, 0);
    cp_commit();

    for (int jt = 0; jt < nt; jt++) {
        const int buf = jt & 1;
        if (jt + 1 < nt) {
            loadKV(buf ^ 1, jt + 1);
            cp_commit();
            cp_wait<1>();
        } else {
            cp_wait<0>();
        }
        __syncthreads();

        const int jb = jt * 64;

#pragma unroll
        for (int g = 0; g < 2; g++) {
            const int jg = jb + g * 32;
            const int jrel = qbase + 31 - jg;
            if (jrel < 0) continue;                      // group fully masked
            const int kliml = min(2, (jrel >> 4) + 1);   // PV k-steps in group
            const int nliml = min(4, (jrel >> 3) + 1);   // QK n-tiles in group
            const int nlim2 = 2 * kliml;                 // exp/mask range
            const bool needMask = (jg + 31 > qbase);

            // ---- S = Q @ K^T : K fragment shared across both q halves ----
            float s0[4][4], s1[4][4];
#pragma unroll
            for (int n8 = 0; n8 < 4; n8++)
#pragma unroll
                for (int e = 0; e < 4; e++) { s0[n8][e] = 0.f; s1[n8][e] = 0.f; }

#pragma unroll
            for (int kk = 0; kk < 4; kk++) {
#pragma unroll
                for (int npl = 0; npl < 2; npl++) {
                    if (2 * npl < nliml) {
                        uint32_t r[4];
                        ldmatrix_x4(r, &Ks[buf][(g * 2 + npl) * 16 + mrow][kk * 16 + mcol]);
                        mma_f16(s0[2 * npl], qf0[kk], r);
                        mma_f16(s1[2 * npl], qf1[kk], r);
                        if (2 * npl + 1 < nliml) {
                            mma_f16(s0[2 * npl + 1], qf0[kk], r + 2);
                            mma_f16(s1[2 * npl + 1], qf1[kk], r + 2);
                        }
                    }
                }
            }

            // ---- causal mask (global indices) ----
            if (needMask) {
#pragma unroll
                for (int n8 = 0; n8 < 4; n8++) {
                    if (n8 < nlim2) {
                        int j0 = jg + n8 * 8 + (lane & 3) * 2;
                        if (j0     > rq0)      s0[n8][0] = -INFINITY;
                        if (j0 + 1 > rq0)      s0[n8][1] = -INFINITY;
                        if (j0     > rq0 + 8)  s0[n8][2] = -INFINITY;
                        if (j0 + 1 > rq0 + 8)  s0[n8][3] = -INFINITY;
                        if (j0     > rq0 + 16) s1[n8][0] = -INFINITY;
                        if (j0 + 1 > rq0 + 16) s1[n8][1] = -INFINITY;
                        if (j0     > rq0 + 24) s1[n8][2] = -INFINITY;
                        if (j0 + 1 > rq0 + 24) s1[n8][3] = -INFINITY;
                    }
                }
            }

            // ---- zero-shift exp (s dies here) ----
            uint32_t Pa01[4], Pa23[4], Pb01[4], Pb23[4];
#pragma unroll
            for (int n8 = 0; n8 < 4; n8++) {
                if (n8 < nlim2) {
                    Pa01[n8] = h2ex2(packh2(s0[n8][0] * L2E, s0[n8][1] * L2E));
                    Pa23[n8] = h2ex2(packh2(s0[n8][2] * L2E, s0[n8][3] * L2E));
                    Pb01[n8] = h2ex2(packh2(s1[n8][0] * L2E, s1[n8][1] * L2E));
                    Pb23[n8] = h2ex2(packh2(s1[n8][2] * L2E, s1[n8][3] * L2E));
                }
            }

            // ---- ctx += P @ V : V fragment shared across both q halves ----
#pragma unroll
            for (int kkl = 0; kkl < 2; kkl++) {
                if (kkl < kliml) {
                    uint32_t a0[4], a1[4];
                    a0[0] = Pa01[2 * kkl];     a0[1] = Pa23[2 * kkl];
                    a0[2] = Pa01[2 * kkl + 1]; a0[3] = Pa23[2 * kkl + 1];
                    a1[0] = Pb01[2 * kkl];     a1[1] = Pb23[2 * kkl];
                    a1[2] = Pb01[2 * kkl + 1]; a1[3] = Pb23[2 * kkl + 1];
                    const int kc = (g * 2 + kkl) * 16 + mcol;
#pragma unroll
                    for (int np = 0; np < 4; np++) {
                        uint32_t r[4];
                        ldmatrix_x4(r, &Vs[buf][np * 16 + mrow][kc]);
                        mma_f16(o0[2 * np],     a0, r);
                        mma_f16(o0[2 * np + 1], a0, r + 2);
                        mma_f16(o1[2 * np],     a1, r);
                        mma_f16(o1[2 * np + 1], a1, r + 2);
                    }
                    mma_f16(o0[8], a0, bl);
                    mma_f16(o1[8], a1, bl);
                }
            }
        }
        __syncthreads();
    }

    // finalize: l in [8][0]/[8][2] of quad-leader lanes
    const float l00 = __shfl_sync(0xffffffff, o0[8][0], lane & 28);
    const float l01 = __shfl_sync(0xffffffff, o0[8][2], lane & 28);
    const float l10 = __shfl_sync(0xffffffff, o1[8][0], lane & 28);
    const float l11 = __shfl_sync(0xffffffff, o1[8][2], lane & 28);
    const float i00 = 1.f / l00, i01 = 1.f / l01;
    const float i10 = 1.f / l10, i11 = 1.f / l11;

#pragma unroll
    for (int n8 = 0; n8 < 8; n8++) {
        int col = h * HDIM + n8 * 8 + (lane & 3) * 2;
        *(__half2*)(O + (size_t)rq0 * D_Q + col) =
            __floats2half2_rn(o0[n8][0] * i00, o0[n8][1] * i00);
        *(__half2*)(O + (size_t)(rq0 + 8) * D_Q + col) =
            __floats2half2_rn(o0[n8][2] * i01, o0[n8][3] * i01);
        *(__half2*)(O + (size_t)(rq0 + 16) * D_Q + col) =
            __floats2half2_rn(o1[n8][0] * i10, o1[n8][1] * i10);
        *(__half2*)(O + (size_t)(rq0 + 24) * D_Q + col) =
            __floats2half2_rn(o1[n8][2] * i11, o1[n8][3] * i11);
    }
}

// ---------------------------------------------------------------------------
extern "C" void kernel_launch(void* const* d_in, const int* in_sizes, int n_in,
                              void* d_out, int out_size)
{
    const float* x  = (const float*)d_in[0];
    const float* Wq = (const float*)d_in[1];
    const float* Wk = (const float*)d_in[2];
    const float* Wv = (const float*)d_in[3];
    const float* Wo = (const float*)d_in[4];
    const float* bo = (const float*)d_in[5];
    float* out = (float*)d_out;

    __half *xh, *wqkT, *wvT, *woT, *qh, *kh, *vt, *ctx;
    cudaGetSymbolAddress((void**)&xh,   g_xh);
    cudaGetSymbolAddress((void**)&wqkT, g_wqkT);
    cudaGetSymbolAddress((void**)&wvT,  g_wvT);
    cudaGetSymbolAddress((void**)&woT,  g_woT);
    cudaGetSymbolAddress((void**)&qh,   g_qh);
    cudaGetSymbolAddress((void**)&kh,   g_kh);
    cudaGetSymbolAddress((void**)&vt,   g_vt);
    cudaGetSymbolAddress((void**)&ctx,  g_ctx);

    // one-time formatting: single fused launch
    prep_kernel<<<PREP_BLOCKS, 256>>>(x, Wq, Wk, Wv, Wo, xh, wqkT, wvT, woT);

    // merged Q | K | V^T projections
    gemm_h_kernel<3><<<dim3(24, 32), 128>>>(
        xh, wqkT, wvT, nullptr, qh, kh, vt, D_Q + D_KV, D_IN);

    // attention (GQA-shared KV tiles, 32 q-rows/warp, grouped softmax)
    flash_attn_tc_kernel<<<dim3(S_LEN / 64, N_KV, 2), 128>>>(qh, kh, vt, ctx);

    // output projection + bias
    gemm_h_kernel<0><<<dim3(16, 32), 128>>>(
        ctx, woT, nullptr, bo, out, nullptr, nullptr, D_Q, D_IN);
}